// round 12
// baseline (speedup 1.0000x reference)
#include <cuda_runtime.h>
#include <cuda_bf16.h>
#include <cstdint>

// SConv2dAvg = HMMA GEMM fed by a one-time NCHW->NHWC bf16-split transpose.
// g_T[b][ih][iw] = [hi c0..63 (128B) | lo c0..63 (128B)]  (256B per site)
// Main kernel: per CTA n = 16 b x 16 px = 256 cols; K=576 as 18 k32 chunks
// (k' = (r*3+s)*64 + c). 3-product split: Whi*Phi + Whi*Plo + Wlo*Phi.
// Gather = contiguous 16B cp.async, double-buffered; zero cross-phase registers.

#define Y_DIM   63
#define COUT    64
#define KTOT    576
#define THREADS 256

// per-buffer: B 256 rows x 144B (hi|lo|pad) @0, A 64 rows x 144B @36864
#define BUFSZ   46080
#define A_IN_BUF 36864
#define SMEM_TOTAL (2 * BUFSZ)   // 92160

__device__ unsigned short g_A[18 * 64 * 64];        // [ch][m(64)][hi 32 | lo 32]
__device__ char           g_T[16 * 128 * 128 * 256]; // 64MB NHWC bf16 hi|lo

__global__ void prep_A_kernel(const float* __restrict__ w) {
    int idx = blockIdx.x * 256 + threadIdx.x;
    if (idx >= COUT * KTOT) return;
    int o  = idx / KTOT;
    int kp = idx - o * KTOT;        // k' = rs*64 + c
    int rs = kp >> 6;
    int c  = kp & 63;
    float v = w[o * KTOT + c * 9 + rs];
    unsigned short hi;
    asm("cvt.rn.bf16.f32 %0, %1;" : "=h"(hi) : "f"(v));
    float rem = v - __uint_as_float(((unsigned)hi) << 16);
    unsigned short lo;
    asm("cvt.rn.bf16.f32 %0, %1;" : "=h"(lo) : "f"(rem));
    int ch = rs * 2 + (c >> 5);
    int cc = c & 31;
    g_A[ch * 4096 + o * 64 + cc]      = hi;
    g_A[ch * 4096 + o * 64 + 32 + cc] = lo;
}

__device__ __forceinline__ uint32_t pack_bf16x2(float x, float y) {
    uint32_t r;
    asm("cvt.rn.satfinite.bf16x2.f32 %0, %2, %1;" : "=r"(r) : "f"(x), "f"(y));
    return r;
}

// NCHW fp32 -> NHWC bf16 hi|lo. Block = (b, ih); thread = (iw = tid>>1, h = tid&1).
__global__ __launch_bounds__(256) void transpose_kernel(const float* __restrict__ in) {
    int bidx = blockIdx.x;              // b*128 + ih
    int b  = bidx >> 7;
    int ih = bidx & 127;
    int tid = threadIdx.x;
    int iw = tid >> 1;
    int h  = tid & 1;                   // c-half: c = h*32 + i

    const float* src = in + ((long)(b * 64 + h * 32) << 14) + ih * 128 + iw;

    float v[32];
#pragma unroll
    for (int i = 0; i < 32; i++)
        v[i] = __ldg(src + ((long)i << 14));

    uint32_t hp[16], lp[16];
#pragma unroll
    for (int q = 0; q < 16; q++) {
        float a0 = v[2 * q], a1 = v[2 * q + 1];
        hp[q] = pack_bf16x2(a0, a1);
        float r0 = a0 - __uint_as_float(hp[q] << 16);
        float r1 = a1 - __uint_as_float(hp[q] & 0xFFFF0000u);
        lp[q] = pack_bf16x2(r0, r1);
    }

    char* dst = g_T + (long)bidx * 32768 + iw * 256 + h * 64;
#pragma unroll
    for (int q = 0; q < 4; q++) {
        *(uint4*)(dst + q * 16)       = make_uint4(hp[4*q], hp[4*q+1], hp[4*q+2], hp[4*q+3]);
        *(uint4*)(dst + 128 + q * 16) = make_uint4(lp[4*q], lp[4*q+1], lp[4*q+2], lp[4*q+3]);
    }
}

#define MMA(acc, a, b)                                                         \
    asm volatile("mma.sync.aligned.m16n8k16.row.col.f32.bf16.bf16.f32 "        \
        "{%0,%1,%2,%3}, {%4,%5,%6,%7}, {%8,%9}, {%0,%1,%2,%3};"                \
        : "+f"((acc)[0]), "+f"((acc)[1]), "+f"((acc)[2]), "+f"((acc)[3])       \
        : "r"((a)[0]), "r"((a)[1]), "r"((a)[2]), "r"((a)[3]),                  \
          "r"((b)[0]), "r"((b)[1]))

#define CP16(dst, src)                                                         \
    asm volatile("cp.async.cg.shared.global [%0], [%1], 16;"                   \
        :: "r"(dst), "l"(src) : "memory")

// issue chunk ch's B (8 cp) + A (2 cp) into buffer bu
#define ISSUE(ch, bu) do {                                                     \
    int rs_ = (ch) >> 1;                                                       \
    int r_  = rs_ / 3, s_ = rs_ - r_ * 3;                                      \
    const char* tr_ = tB + (r_ << 15) + (s_ << 8) + (((ch) & 1) << 6);         \
    uint32_t bd_ = sb + (bu) * BUFSZ + tid * 144;                              \
    _Pragma("unroll") for (int j_ = 0; j_ < 4; j_++)                           \
        CP16(bd_ + j_ * 16, tr_ + j_ * 16);                                    \
    _Pragma("unroll") for (int j_ = 0; j_ < 4; j_++)                           \
        CP16(bd_ + 64 + j_ * 16, tr_ + 128 + j_ * 16);                         \
    _Pragma("unroll") for (int i_ = 0; i_ < 2; i_++) {                         \
        int e_ = tid + i_ * 256;                                               \
        int m_ = e_ >> 3, j_ = e_ & 7;                                         \
        CP16(sb + (bu) * BUFSZ + A_IN_BUF + m_ * 144 + j_ * 16,                \
             (const char*)g_A + (ch) * 8192 + m_ * 128 + j_ * 16);             \
    }                                                                          \
    asm volatile("cp.async.commit_group;" ::: "memory");                       \
} while (0)

// one k16 step from buffer base pointers Bb/Ab (144B rows, hi@0 lo@+64)
#define COMPUTE_KQ(kq) do {                                                    \
    uint32_t bh_[4][2], bl_[4][2];                                             \
    _Pragma("unroll") for (int nf = 0; nf < 4; nf++) {                         \
        const char* pb = Bb + (w * 32 + nf * 8 + fr) * 144 + (kq) * 32 + fq * 4; \
        bh_[nf][0] = *(const uint32_t*)pb;                                     \
        bh_[nf][1] = *(const uint32_t*)(pb + 16);                              \
        bl_[nf][0] = *(const uint32_t*)(pb + 64);                              \
        bl_[nf][1] = *(const uint32_t*)(pb + 64 + 16);                         \
    }                                                                          \
    _Pragma("unroll") for (int mf = 0; mf < 4; mf++) {                         \
        const char* pa = Ab + (mf * 16 + fr) * 144 + (kq) * 32 + fq * 4;       \
        uint32_t ah_[4], al_[4];                                               \
        ah_[0] = *(const uint32_t*)pa;                                         \
        ah_[1] = *(const uint32_t*)(pa + 8 * 144);                             \
        ah_[2] = *(const uint32_t*)(pa + 16);                                  \
        ah_[3] = *(const uint32_t*)(pa + 8 * 144 + 16);                        \
        al_[0] = *(const uint32_t*)(pa + 64);                                  \
        al_[1] = *(const uint32_t*)(pa + 64 + 8 * 144);                        \
        al_[2] = *(const uint32_t*)(pa + 64 + 16);                             \
        al_[3] = *(const uint32_t*)(pa + 64 + 8 * 144 + 16);                   \
        _Pragma("unroll") for (int nf = 0; nf < 4; nf++) {                     \
            MMA(acc[mf][nf], ah_, bh_[nf]);                                    \
            MMA(acc[mf][nf], ah_, bl_[nf]);                                    \
            MMA(acc[mf][nf], al_, bh_[nf]);                                    \
        }                                                                      \
    }                                                                          \
} while (0)

__global__ __launch_bounds__(THREADS, 2) void sconv_hmma_kernel(
    const float* __restrict__ bias,
    const int*   __restrict__ selh,
    const int*   __restrict__ selw,
    float*       __restrict__ out)
{
    extern __shared__ char smem[];
    const uint32_t sb = (uint32_t)__cvta_generic_to_shared(smem);

    const int tid  = threadIdx.x;
    const int lane = tid & 31;
    const int w    = tid >> 5;
    const int fq   = lane & 3;
    const int fr   = lane >> 2;

    const int y   = blockIdx.x >> 2;
    const int px0 = (blockIdx.x & 3) * 16;

    // gather mapping: thread owns B row tid = b*16 + pxl
    const int b   = tid >> 4;
    const int pxl = tid & 15;
    const int pxc = min(px0 + pxl, Y_DIM - 1);
    const int sh  = selh[y * Y_DIM + pxc];
    const int sw  = selw[y * Y_DIM + pxc];
    const char* tB = g_T + ((long)b << 22)
                   + ((long)(2 * y + sh) << 15) + ((2 * pxc + sw) << 8);

    float acc[4][4][4];
#pragma unroll
    for (int i = 0; i < 4; i++)
#pragma unroll
        for (int j = 0; j < 4; j++)
#pragma unroll
            for (int q = 0; q < 4; q++) acc[i][j][q] = 0.f;

    ISSUE(0, 0);

    for (int ch = 0; ch < 18; ch++) {
        const int bu = ch & 1;
        if (ch < 17) ISSUE(ch + 1, bu ^ 1);
        if (ch < 17)
            asm volatile("cp.async.wait_group 1;" ::: "memory");
        else
            asm volatile("cp.async.wait_group 0;" ::: "memory");
        __syncthreads();                         // all threads' cp data visible

        const char* Bb = smem + bu * BUFSZ;
        const char* Ab = smem + bu * BUFSZ + A_IN_BUF;
        COMPUTE_KQ(0);
        COMPUTE_KQ(1);
        __syncthreads();                         // done reading before next overwrite
    }

    // ---- epilogue: scalar stores (odd output strides) ----
    const int npx   = min(16, Y_DIM - px0);
    const int ybase = y * Y_DIM + px0;

#pragma unroll
    for (int mf = 0; mf < 4; mf++) {
        const int o = mf * 16 + fr;
        const float bo0 = __ldg(bias + o);
        const float bo8 = __ldg(bias + o + 8);
#pragma unroll
        for (int nf = 0; nf < 4; nf++) {
            int n    = w * 32 + nf * 8 + 2 * fq;
            int bcol = n >> 4;
            int pp   = n & 15;
            long base0 = ((long)(bcol * COUT + o)) * (Y_DIM * Y_DIM) + ybase + pp;
            long base8 = base0 + 8L * (Y_DIM * Y_DIM);
            if (pp < npx) {
                out[base0] = acc[mf][nf][0] + bo0;
                out[base8] = acc[mf][nf][2] + bo8;
            }
            if (pp + 1 < npx) {
                out[base0 + 1] = acc[mf][nf][1] + bo0;
                out[base8 + 1] = acc[mf][nf][3] + bo8;
            }
        }
    }
}

extern "C" void kernel_launch(void* const* d_in, const int* in_sizes, int n_in,
                              void* d_out, int out_size)
{
    const float* input  = (const float*)d_in[0];
    const float* weight = (const float*)d_in[1];
    const float* bias   = (const float*)d_in[2];
    const int*   selh   = (const int*)d_in[3];
    const int*   selw   = (const int*)d_in[4];
    float*       out    = (float*)d_out;

    cudaFuncSetAttribute(sconv_hmma_kernel,
                         cudaFuncAttributeMaxDynamicSharedMemorySize, SMEM_TOTAL);

    prep_A_kernel<<<(COUT * KTOT + 255) / 256, 256>>>(weight);
    transpose_kernel<<<16 * 128, 256>>>(input);
    sconv_hmma_kernel<<<Y_DIM * 4, THREADS, SMEM_TOTAL>>>(bias, selh, selw, out);
}

// round 13
// speedup vs baseline: 1.3182x; 1.3182x over previous
#include <cuda_runtime.h>
#include <cuda_bf16.h>
#include <cstdint>

// SConv2dAvg as warp-specialized HMMA GEMM (producer/consumer ring).
// D[o,n] = sum_k W[o,k] P[k,n]; per CTA n = 8 batches x 16 px = 128 cols.
// K=576 in 9 chunks of 64 (one (r,s) plane each). 3-product bf16 split.
// 12 warps: 8 consumers (m64 x n16), 4 producers (gather+convert, 2-stage ring).

#define Y_DIM   63
#define COUT    64
#define KTOT    576
#define THREADS 384

// stage: B 128 rows x 272B ([hi 128|lo 128|pad 16]) @0; A 64 rows x 272B @34816
#define STAGE   52224
#define A_IN    34816
#define SMEM_TOTAL (2 * STAGE)   // 104448

// named barriers: empty0=0 empty1=1 full0=2 full1=3, count = all 384 threads
#define BSYNC(id) asm volatile("bar.sync %0, 384;"   :: "r"(id))
#define BARR(id)  asm volatile("bar.arrive %0, 384;" :: "r"(id))

__device__ unsigned short g_A[9 * 64 * 128];   // [ch][m 64][hi 64c | lo 64c]

__global__ void prep_A_kernel(const float* __restrict__ w) {
    int idx = blockIdx.x * 256 + threadIdx.x;
    if (idx >= COUT * KTOT) return;
    int o  = idx / KTOT;
    int kp = idx - o * KTOT;        // k' = rs*64 + c
    int rs = kp >> 6;
    int c  = kp & 63;
    float v = w[o * KTOT + c * 9 + rs];
    unsigned short hi;
    asm("cvt.rn.bf16.f32 %0, %1;" : "=h"(hi) : "f"(v));
    float rem = v - __uint_as_float(((unsigned)hi) << 16);
    unsigned short lo;
    asm("cvt.rn.bf16.f32 %0, %1;" : "=h"(lo) : "f"(rem));
    g_A[rs * 8192 + o * 128 + c]      = hi;
    g_A[rs * 8192 + o * 128 + 64 + c] = lo;
}

__device__ __forceinline__ uint32_t pack_bf16x2(float x, float y) {
    uint32_t r;
    asm("cvt.rn.satfinite.bf16x2.f32 %0, %2, %1;" : "=r"(r) : "f"(x), "f"(y));
    return r;
}

#define MMA(acc, a, b)                                                         \
    asm volatile("mma.sync.aligned.m16n8k16.row.col.f32.bf16.bf16.f32 "        \
        "{%0,%1,%2,%3}, {%4,%5,%6,%7}, {%8,%9}, {%0,%1,%2,%3};"                \
        : "+f"((acc)[0]), "+f"((acc)[1]), "+f"((acc)[2]), "+f"((acc)[3])       \
        : "r"((a)[0]), "r"((a)[1]), "r"((a)[2]), "r"((a)[3]),                  \
          "r"((b)[0]), "r"((b)[1]))

#define CP16(dst, src)                                                         \
    asm volatile("cp.async.cg.shared.global [%0], [%1], 16;"                   \
        :: "r"(dst), "l"(src) : "memory")

// producer: load 16 c-values (round g) of this thread's B row
#define LDG16(v, g)                                                            \
    _Pragma("unroll") for (int j_ = 0; j_ < 16; j_++)                          \
        (v)[j_] = __ldg(src + ((((g) << 4) + j_) << 14));

// producer: convert round g -> 32B hi @ p*272+g*32, 32B lo @ +128
#define CVTS(v, g) do {                                                        \
    uint32_t hp_[8], lp_[8];                                                   \
    _Pragma("unroll") for (int q_ = 0; q_ < 8; q_++) {                         \
        float a0_ = (v)[2 * q_], a1_ = (v)[2 * q_ + 1];                        \
        hp_[q_] = pack_bf16x2(a0_, a1_);                                       \
        float r0_ = a0_ - __uint_as_float(hp_[q_] << 16);                      \
        float r1_ = a1_ - __uint_as_float(hp_[q_] & 0xFFFF0000u);              \
        lp_[q_] = pack_bf16x2(r0_, r1_);                                       \
    }                                                                          \
    char* d_ = Bst + p * 272 + (g) * 32;                                       \
    *(uint4*)d_         = make_uint4(hp_[0], hp_[1], hp_[2], hp_[3]);          \
    *(uint4*)(d_ + 16)  = make_uint4(hp_[4], hp_[5], hp_[6], hp_[7]);          \
    *(uint4*)(d_ + 128) = make_uint4(lp_[0], lp_[1], lp_[2], lp_[3]);          \
    *(uint4*)(d_ + 144) = make_uint4(lp_[4], lp_[5], lp_[6], lp_[7]);          \
} while (0)

// consumer: one k16 step from stage (Bb, Ab); 272B rows, hi@0 lo@+128
#define COMPUTE_KQ(kq) do {                                                    \
    uint32_t bh_[2][2], bl_[2][2];                                             \
    _Pragma("unroll") for (int nf = 0; nf < 2; nf++) {                         \
        const char* pb = Bb + (w16 + nf * 8 + fr) * 272 + (kq) * 32 + fq4;     \
        bh_[nf][0] = *(const uint32_t*)pb;                                     \
        bh_[nf][1] = *(const uint32_t*)(pb + 16);                              \
        bl_[nf][0] = *(const uint32_t*)(pb + 128);                             \
        bl_[nf][1] = *(const uint32_t*)(pb + 144);                             \
    }                                                                          \
    _Pragma("unroll") for (int mf = 0; mf < 4; mf++) {                         \
        const char* pa = Ab + (mf * 16 + fr) * 272 + (kq) * 32 + fq4;          \
        uint32_t ah_[4], al_[4];                                               \
        ah_[0] = *(const uint32_t*)pa;                                         \
        ah_[1] = *(const uint32_t*)(pa + 8 * 272);                             \
        ah_[2] = *(const uint32_t*)(pa + 16);                                  \
        ah_[3] = *(const uint32_t*)(pa + 8 * 272 + 16);                        \
        al_[0] = *(const uint32_t*)(pa + 128);                                 \
        al_[1] = *(const uint32_t*)(pa + 128 + 8 * 272);                       \
        al_[2] = *(const uint32_t*)(pa + 144);                                 \
        al_[3] = *(const uint32_t*)(pa + 144 + 8 * 272);                       \
        _Pragma("unroll") for (int nf = 0; nf < 2; nf++) {                     \
            MMA(acc[mf][nf], ah_, bh_[nf]);                                    \
            MMA(acc[mf][nf], ah_, bl_[nf]);                                    \
            MMA(acc[mf][nf], al_, bh_[nf]);                                    \
        }                                                                      \
    }                                                                          \
} while (0)

__global__ __launch_bounds__(THREADS, 2) void sconv_hmma_kernel(
    const float* __restrict__ input,
    const float* __restrict__ bias,
    const int*   __restrict__ selh,
    const int*   __restrict__ selw,
    float*       __restrict__ out)
{
    extern __shared__ char smem[];
    const uint32_t sb = (uint32_t)__cvta_generic_to_shared(smem);

    const int tid  = threadIdx.x;
    const int lane = tid & 31;
    const int w    = tid >> 5;

    // grid 504: y, x-tile, batch-half
    const int bid = blockIdx.x;
    const int y   = bid >> 3;
    const int xt  = (bid >> 1) & 3;
    const int bh  = bid & 1;
    const int px0 = xt * 16;

    if (w >= 8) {
        // ================= PRODUCER (warps 8-11, 128 threads) =================
        const int p   = tid - 256;             // B row 0..127
        const int pxl = p & 15;
        const int pxc = min(px0 + pxl, Y_DIM - 1);
        const int sh  = selh[y * Y_DIM + pxc];
        const int sw  = selw[y * Y_DIM + pxc];
        const float* pbase = input + (((bh << 3) + (p >> 4)) << 20)
                           + (2 * y + sh) * 128 + 2 * pxc + sw;

        for (int ch = 0; ch < 9; ch++) {
            const int st = ch & 1;
            if (ch >= 2) BSYNC(st);            // wait stage empty
            char* Bst = smem + st * STAGE;

            // A slab: register-free cp.async (1024 x 16B over 128 threads)
#pragma unroll
            for (int i = 0; i < 8; i++) {
                int e = p + i * 128;
                int m = e >> 4, j = e & 15;
                CP16(sb + st * STAGE + A_IN + m * 272 + j * 16,
                     (const char*)g_A + ch * 16384 + m * 256 + j * 16);
            }
            asm volatile("cp.async.commit_group;" ::: "memory");

            // B gather: 64 LDG in 4 rounds, 2-round pipelined
            const float* src = pbase + (ch / 3) * 128 + (ch - (ch / 3) * 3);
            {
                float v0[16], v1[16];
                LDG16(v0, 0);
                LDG16(v1, 1);
                CVTS(v0, 0);
                LDG16(v0, 2);
                CVTS(v1, 1);
                LDG16(v1, 3);
                CVTS(v0, 2);
                CVTS(v1, 3);
            }
            asm volatile("cp.async.wait_group 0;" ::: "memory");
            asm volatile("membar.cta;" ::: "memory");
            BARR(2 + st);                      // stage full
        }
        return;
    }

    // ================= CONSUMER (warps 0-7, 256 threads) =================
    const int fq  = lane & 3;
    const int fr  = lane >> 2;
    const int fq4 = fq * 4;
    const int w16 = w * 16;

    float acc[4][2][4];
#pragma unroll
    for (int i = 0; i < 4; i++)
#pragma unroll
        for (int j = 0; j < 2; j++)
#pragma unroll
            for (int q = 0; q < 4; q++) acc[i][j][q] = 0.f;

    for (int ch = 0; ch < 9; ch++) {
        const int st = ch & 1;
        BSYNC(2 + st);                         // wait stage full
        const char* Bb = smem + st * STAGE;
        const char* Ab = Bb + A_IN;
        COMPUTE_KQ(0);
        COMPUTE_KQ(1);
        COMPUTE_KQ(2);
        COMPUTE_KQ(3);
        BARR(st);                              // stage empty
    }

    // ---- epilogue: scalar stores (odd output strides) ----
    const int npx   = min(16, Y_DIM - px0);
    const int ybase = y * Y_DIM + px0;
    const int b     = (bh << 3) + w;           // warp owns one batch

#pragma unroll
    for (int mf = 0; mf < 4; mf++) {
        const int o = mf * 16 + fr;
        const float bo0 = __ldg(bias + o);
        const float bo8 = __ldg(bias + o + 8);
#pragma unroll
        for (int nf = 0; nf < 2; nf++) {
            int pp = nf * 8 + 2 * fq;
            long base0 = ((long)(b * COUT + o)) * (Y_DIM * Y_DIM) + ybase + pp;
            long base8 = base0 + 8L * (Y_DIM * Y_DIM);
            if (pp < npx) {
                out[base0] = acc[mf][nf][0] + bo0;
                out[base8] = acc[mf][nf][2] + bo8;
            }
            if (pp + 1 < npx) {
                out[base0 + 1] = acc[mf][nf][1] + bo0;
                out[base8 + 1] = acc[mf][nf][3] + bo8;
            }
        }
    }
}

extern "C" void kernel_launch(void* const* d_in, const int* in_sizes, int n_in,
                              void* d_out, int out_size)
{
    const float* input  = (const float*)d_in[0];
    const float* weight = (const float*)d_in[1];
    const float* bias   = (const float*)d_in[2];
    const int*   selh   = (const int*)d_in[3];
    const int*   selw   = (const int*)d_in[4];
    float*       out    = (float*)d_out;

    cudaFuncSetAttribute(sconv_hmma_kernel,
                         cudaFuncAttributeMaxDynamicSharedMemorySize, SMEM_TOTAL);

    prep_A_kernel<<<(COUT * KTOT + 255) / 256, 256>>>(weight);
    sconv_hmma_kernel<<<Y_DIM * 8, THREADS, SMEM_TOTAL>>>(input, bias, selh, selw, out);
}